// round 5
// baseline (speedup 1.0000x reference)
#include <cuda_runtime.h>
#include <cuda_bf16.h>
#include <cstdint>

#define Bn   16
#define Nn   16384
#define Sn   4096
#define Kn   16
#define FC   68      // fused channels: 64 points + 3 xyz + 1 pad
#define CMID 16
#define DOUT 128
#define AGGD 1072    // 67*16
#define KPAD 1088    // 34 * 32

// Scratch (no allocations allowed -> __device__ globals; zero-initialized)
__device__ float g_fused[(size_t)Bn * Nn * FC];              // ~71 MB
__device__ __nv_bfloat16 g_Ahi[(size_t)Bn * Sn * KPAD];      // agg hi split
__device__ __nv_bfloat16 g_Alo[(size_t)Bn * Sn * KPAD];      // agg lo split
__device__ __nv_bfloat16 g_Bhi[DOUT * KPAD];                 // wl^T hi split
__device__ __nv_bfloat16 g_Blo[DOUT * KPAD];                 // wl^T lo split

__device__ __forceinline__ uint32_t smem_u32(const void* p) {
    uint32_t a;
    asm("{ .reg .u64 t; cvta.to.shared.u64 t, %1; cvt.u32.u64 %0, t; }" : "=r"(a) : "l"(p));
    return a;
}

#define LDMX4(r0, r1, r2, r3, addr)                                            \
    asm volatile("ldmatrix.sync.aligned.m8n8.x4.shared.b16 {%0,%1,%2,%3}, [%4];" \
                 : "=r"(r0), "=r"(r1), "=r"(r2), "=r"(r3) : "r"(addr))

#define MMA16816(acc, a, b0, b1)                                               \
    asm volatile("mma.sync.aligned.m16n8k16.row.col.f32.bf16.bf16.f32 "        \
                 "{%0,%1,%2,%3},{%4,%5,%6,%7},{%8,%9},{%0,%1,%2,%3};"          \
                 : "+f"((acc)[0]), "+f"((acc)[1]), "+f"((acc)[2]), "+f"((acc)[3]) \
                 : "r"((a)[0]), "r"((a)[1]), "r"((a)[2]), "r"((a)[3]),         \
                   "r"(b0), "r"(b1))

#define CP16(dst, src)                                                         \
    asm volatile("cp.async.cg.shared.global [%0], [%1], 16;" :: "r"(dst), "l"(src))
#define CP_COMMIT() asm volatile("cp.async.commit_group;" ::: "memory")
#define CP_WAIT(n)  asm volatile("cp.async.wait_group %0;" :: "n"(n) : "memory")

// ===========================================================================
// Kernel 0: point-major fused feature array
// ===========================================================================
__global__ void k_fuse(const float* __restrict__ xyz, const float* __restrict__ points)
{
    __shared__ float t[32][69];
    int b = blockIdx.y, n0 = blockIdx.x * 32;
    for (int i = threadIdx.x; i < 68 * 32; i += 256) {
        int c = i >> 5, nn = i & 31;
        int n = n0 + nn;
        float v = 0.f;
        if (c < 64)      v = points[(b * 64 + c) * Nn + n];
        else if (c < 67) v = xyz[(b * 3 + (c - 64)) * Nn + n];
        t[nn][c] = v;
    }
    __syncthreads();
    float* dst = g_fused + ((size_t)b * Nn + n0) * FC;
    for (int i = threadIdx.x; i < 32 * 68; i += 256) {
        dst[i] = t[i / 68][i % 68];
    }
}

// ===========================================================================
// LayerNorm (+ leaky 0.2) helper
// ===========================================================================
template <int NCH>
__device__ __forceinline__ void ln_leaky(float* h, const float* gmm, const float* bt)
{
    const float inv = 1.f / (float)NCH;
    float m = 0.f;
#pragma unroll
    for (int j = 0; j < NCH; j++) m += h[j];
    m *= inv;
    float v = 0.f;
#pragma unroll
    for (int j = 0; j < NCH; j++) { float d = h[j] - m; v += d * d; }
    v *= inv;
    float r = rsqrtf(v + 1e-5f);
#pragma unroll
    for (int j = 0; j < NCH; j++) {
        float y = (h[j] - m) * r * gmm[j] + bt[j];
        h[j] = y > 0.f ? y : 0.2f * y;
    }
}

// ===========================================================================
// Kernel 1: gather + WeightNet + 67x16 aggregation; outputs bf16 hi/lo splits
//   Aggregation: thread = (m-pair p, c-slot t); wk held in registers ->
//   1 LDS per 2 FMAs instead of 3 per 2.
// ===========================================================================
__global__ __launch_bounds__(128)
void k_agg(const int* __restrict__ nn_idx, const float* __restrict__ new_xyz,
           const float* __restrict__ w0, const float* __restrict__ b0,
           const float* __restrict__ gm0, const float* __restrict__ be0,
           const float* __restrict__ w1, const float* __restrict__ b1,
           const float* __restrict__ gm1, const float* __restrict__ be1,
           const float* __restrict__ w2, const float* __restrict__ b2,
           const float* __restrict__ gm2, const float* __restrict__ be2)
{
    __shared__ float g[Kn][FC];
    __shared__ float wk[Kn][17];
    __shared__ int   idxs[Kn];
    __shared__ float nx[3];
    __shared__ float wp[312];

    int s = blockIdx.x, b = blockIdx.y;
    int tid = threadIdx.x;

    if (tid < Kn) idxs[tid] = nn_idx[(b * Sn + s) * Kn + tid];
    if (tid >= 64 && tid < 67) nx[tid - 64] = new_xyz[(b * 3 + (tid - 64)) * Sn + s];

    if (tid < 24) wp[tid] = w0[tid];
    if (tid < 8) {
        wp[24 + tid] = b0[tid];  wp[32 + tid] = gm0[tid]; wp[40 + tid] = be0[tid];
        wp[112 + tid] = b1[tid]; wp[120 + tid] = gm1[tid]; wp[128 + tid] = be1[tid];
    }
    if (tid < 64) wp[48 + tid] = w1[tid];
    wp[136 + tid] = w2[tid];
    if (tid < 16) {
        wp[264 + tid] = b2[tid]; wp[280 + tid] = gm2[tid]; wp[296 + tid] = be2[tid];
    }
    __syncthreads();

    for (int i = tid; i < Kn * (FC / 4); i += 128) {
        int k = i / 17, c = i - k * 17;
        const float4* src = (const float4*)(g_fused + ((size_t)b * Nn + idxs[k]) * FC);
        ((float4*)(&g[k][0]))[c] = src[c];
    }
    __syncthreads();

    if (tid < Kn) {
        int k = tid;
        float x0 = g[k][64] - nx[0], x1 = g[k][65] - nx[1], x2 = g[k][66] - nx[2];
        g[k][64] = x0; g[k][65] = x1; g[k][66] = x2;

        float h[8];
#pragma unroll
        for (int j = 0; j < 8; j++)
            h[j] = x0 * wp[j] + x1 * wp[8 + j] + x2 * wp[16 + j] + wp[24 + j];
        ln_leaky<8>(h, wp + 32, wp + 40);

        float h2[8];
#pragma unroll
        for (int j = 0; j < 8; j++) {
            float a = wp[112 + j];
#pragma unroll
            for (int r = 0; r < 8; r++) a += h[r] * wp[48 + r * 8 + j];
            h2[j] = a;
        }
        ln_leaky<8>(h2, wp + 120, wp + 128);

        float h3[16];
#pragma unroll
        for (int j = 0; j < 16; j++) {
            float a = wp[264 + j];
#pragma unroll
            for (int r = 0; r < 8; r++) a += h2[r] * wp[136 + r * 16 + j];
            h3[j] = a;
        }
        ln_leaky<16>(h3, wp + 280, wp + 296);
#pragma unroll
        for (int j = 0; j < 16; j++) wk[k][j] = h3[j];
    }
    __syncthreads();

    // ---- aggregation: p = m-pair (0..7), t = c-slot (0..15) ----
    int p = tid >> 4, t = tid & 15;
    float wr0[Kn], wr1[Kn];
#pragma unroll
    for (int k = 0; k < Kn; k++) { wr0[k] = wk[k][2 * p]; wr1[k] = wk[k][2 * p + 1]; }

    uint32_t* hrow = (uint32_t*)(g_Ahi + ((size_t)b * Sn + s) * KPAD);
    uint32_t* lrow = (uint32_t*)(g_Alo + ((size_t)b * Sn + s) * KPAD);
    for (int c = t; c < 67; c += 16) {
        float s0 = 0.f, s1 = 0.f;
#pragma unroll
        for (int k = 0; k < Kn; k++) {
            float fv = g[k][c];
            s0 += fv * wr0[k];
            s1 += fv * wr1[k];
        }
        __nv_bfloat16 h0 = __float2bfloat16(s0);
        __nv_bfloat16 h1 = __float2bfloat16(s1);
        __nv_bfloat16 l0 = __float2bfloat16(s0 - __bfloat162float(h0));
        __nv_bfloat16 l1 = __float2bfloat16(s1 - __bfloat162float(h1));
        int ip = c * 8 + p;
        hrow[ip] = (uint32_t)*(unsigned short*)&h0 | ((uint32_t)*(unsigned short*)&h1 << 16);
        lrow[ip] = (uint32_t)*(unsigned short*)&l0 | ((uint32_t)*(unsigned short*)&l1 << 16);
    }
}

// ===========================================================================
// Kernel 1.5: transpose wl [1072][128] -> [128][1088], split bf16 hi/lo
// ===========================================================================
__global__ void k_prepB(const float* __restrict__ wl)
{
    int idx = blockIdx.x * 256 + threadIdx.x;
    if (idx >= DOUT * KPAD) return;
    int n = idx / KPAD, k = idx - n * KPAD;
    float v = (k < AGGD) ? wl[k * DOUT + n] : 0.f;
    __nv_bfloat16 h = __float2bfloat16(v);
    __nv_bfloat16 l = __float2bfloat16(v - __bfloat162float(h));
    g_Bhi[idx] = h;
    g_Blo[idx] = l;
}

// ===========================================================================
// Kernel 2: pipelined mma.sync bf16x3 GEMM [65536,1088]x[1088,128]
//   CTA 256 thr (8 warps: 2m x 4n, warp tile 32x32), CTA tile 64x128.
//   K: 34 chunks of 32; cp.async double buffer, ONE barrier per chunk.
//   MMAs grouped by term (HH/HL/LH): accumulator reuse distance = 8.
// ===========================================================================
#define PITCHB   48          // bytes per smem row
#define A_SUB    3072        // 64 rows * 48B
#define B_SUB    6144        // 128 rows * 48B
#define B_BASE   12288
#define STAGEB   36864
#define GEMM_SMEM (2 * STAGEB)
#define TPITCH   129

__global__ __launch_bounds__(256, 3)
void k_gemm_mma(const float* __restrict__ bl, const float* __restrict__ gl,
                const float* __restrict__ bel, float* __restrict__ out)
{
    extern __shared__ char dsm[];
    __shared__ float spb[DOUT], spg[DOUT], spe[DOUT];

    int tid = threadIdx.x;
    int wid = tid >> 5, lane = tid & 31;
    int wm = wid & 1, wn = wid >> 1;       // warp tile rows wm*32, cols wn*32
    int m0 = blockIdx.x * 64;

    if (tid < DOUT) { spb[tid] = bl[tid]; spg[tid] = gl[tid]; spe[tid] = bel[tid]; }

    uint32_t sb = smem_u32(dsm);
    uint32_t aOff = (uint32_t)((lane & 15) * PITCHB + (lane >> 4) * 16);
    uint32_t bOff = (uint32_t)(((lane >> 4) * 8 + (lane & 7)) * PITCHB + ((lane >> 3) & 1) * 16);

    float acc[2][4][4];
#pragma unroll
    for (int f = 0; f < 2; f++)
#pragma unroll
        for (int q = 0; q < 4; q++)
#pragma unroll
            for (int r = 0; r < 4; r++) acc[f][q][r] = 0.f;

    auto stage_copy = [&](int st, int c) {
        uint32_t stu = sb + st * STAGEB;
#pragma unroll
        for (int t = tid; t < 512; t += 256) {          // A: hi/lo, 2 sub, 64 rows, 2 halves
            int p = t >> 8, rem = t & 255, j = rem >> 7, r2 = rem & 127;
            int r = r2 >> 1, h = r2 & 1;
            const __nv_bfloat16* gA = p ? g_Alo : g_Ahi;
            const __nv_bfloat16* src = gA + (size_t)(m0 + r) * KPAD + c * 32 + j * 16 + h * 8;
            CP16(stu + (p * 2 + j) * A_SUB + r * PITCHB + h * 16, (const void*)src);
        }
#pragma unroll
        for (int t = tid; t < 1024; t += 256) {         // B: hi/lo, 2 sub, 128 rows, 2 halves
            int p = t >> 9, rem = t & 511, j = rem >> 8, r2 = rem & 255;
            int n = r2 >> 1, h = r2 & 1;
            const __nv_bfloat16* gB = p ? g_Blo : g_Bhi;
            const __nv_bfloat16* src = gB + (size_t)n * KPAD + c * 32 + j * 16 + h * 8;
            CP16(stu + B_BASE + (p * 2 + j) * B_SUB + n * PITCHB + h * 16, (const void*)src);
        }
    };

    stage_copy(0, 0);
    CP_COMMIT();

    for (int c = 0; c < 34; c++) {
        CP_WAIT(0);
        __syncthreads();
        if (c + 1 < 34) { stage_copy((c + 1) & 1, c + 1); CP_COMMIT(); }

        uint32_t stu = sb + (c & 1) * STAGEB;
#pragma unroll
        for (int j = 0; j < 2; j++) {
            uint32_t ahi[2][4], alo[2][4], bh[2][4], blw[2][4];
#pragma unroll
            for (int f = 0; f < 2; f++) {
                uint32_t ra = (uint32_t)((wm * 32 + f * 16) * PITCHB) + aOff;
                LDMX4(ahi[f][0], ahi[f][1], ahi[f][2], ahi[f][3], stu + j * A_SUB + ra);
                LDMX4(alo[f][0], alo[f][1], alo[f][2], alo[f][3], stu + (2 + j) * A_SUB + ra);
            }
#pragma unroll
            for (int g = 0; g < 2; g++) {
                uint32_t rb = (uint32_t)((wn * 32 + g * 16) * PITCHB) + bOff;
                LDMX4(bh[g][0],  bh[g][1],  bh[g][2],  bh[g][3],  stu + B_BASE + j * B_SUB + rb);
                LDMX4(blw[g][0], blw[g][1], blw[g][2], blw[g][3], stu + B_BASE + (2 + j) * B_SUB + rb);
            }
            // HH term (8 MMAs, distinct accumulators)
#pragma unroll
            for (int g = 0; g < 2; g++)
#pragma unroll
                for (int f = 0; f < 2; f++) {
                    MMA16816(acc[f][2 * g],     ahi[f], bh[g][0], bh[g][1]);
                    MMA16816(acc[f][2 * g + 1], ahi[f], bh[g][2], bh[g][3]);
                }
            // HL term
#pragma unroll
            for (int g = 0; g < 2; g++)
#pragma unroll
                for (int f = 0; f < 2; f++) {
                    MMA16816(acc[f][2 * g],     ahi[f], blw[g][0], blw[g][1]);
                    MMA16816(acc[f][2 * g + 1], ahi[f], blw[g][2], blw[g][3]);
                }
            // LH term
#pragma unroll
            for (int g = 0; g < 2; g++)
#pragma unroll
                for (int f = 0; f < 2; f++) {
                    MMA16816(acc[f][2 * g],     alo[f], bh[g][0], bh[g][1]);
                    MMA16816(acc[f][2 * g + 1], alo[f], bh[g][2], bh[g][3]);
                }
        }
    }
    __syncthreads();     // all warps done with stage buffers before reusing dsm as T

    // ---- epilogue: acc (+bias) -> T[64][129] ----
    float* T = (float*)dsm;
#pragma unroll
    for (int f = 0; f < 2; f++) {
        int r0 = wm * 32 + f * 16 + (lane >> 2);
#pragma unroll
        for (int q = 0; q < 4; q++) {
            int d = wn * 32 + q * 8 + (lane & 3) * 2;
            T[r0 * TPITCH + d]           = acc[f][q][0] + spb[d];
            T[r0 * TPITCH + d + 1]       = acc[f][q][1] + spb[d + 1];
            T[(r0 + 8) * TPITCH + d]     = acc[f][q][2] + spb[d];
            T[(r0 + 8) * TPITCH + d + 1] = acc[f][q][3] + spb[d + 1];
        }
    }
    __syncthreads();

    // ---- LayerNorm: 4 lanes per row (32 cols each) ----
    {
        int r = tid >> 2, q = tid & 3;
        float v[32];
        float s1 = 0.f, s2 = 0.f;
#pragma unroll
        for (int i = 0; i < 32; i++) {
            v[i] = T[r * TPITCH + q * 32 + i];
            s1 += v[i]; s2 += v[i] * v[i];
        }
        s1 += __shfl_xor_sync(0xffffffffu, s1, 1);
        s2 += __shfl_xor_sync(0xffffffffu, s2, 1);
        s1 += __shfl_xor_sync(0xffffffffu, s1, 2);
        s2 += __shfl_xor_sync(0xffffffffu, s2, 2);
        float mean = s1 * (1.f / 128.f);
        float var  = s2 * (1.f / 128.f) - mean * mean;
        float rs   = rsqrtf(var + 1e-5f);
#pragma unroll
        for (int i = 0; i < 32; i++) {
            int d = q * 32 + i;
            float y = (v[i] - mean) * rs * spg[d] + spe[d];
            T[r * TPITCH + d] = y > 0.f ? y : 0.2f * y;
        }
    }
    __syncthreads();

    // ---- coalesced transposed store ----
    int b = m0 >> 12, s0 = m0 & 4095;
    float* ob = out + (size_t)b * DOUT * Sn + s0;
    for (int i = tid; i < 64 * DOUT; i += 256) {
        int d = i >> 6, r = i & 63;
        ob[(size_t)d * Sn + r] = T[r * TPITCH + d];
    }
}

// ===========================================================================
extern "C" void kernel_launch(void* const* d_in, const int* in_sizes, int n_in,
                              void* d_out, int out_size)
{
    const float* xyz     = (const float*)d_in[0];
    const float* points  = (const float*)d_in[1];
    const float* new_xyz = (const float*)d_in[2];
    const int*   nn_idx  = (const int*)  d_in[3];
    const float* w0  = (const float*)d_in[4];
    const float* b0  = (const float*)d_in[5];
    const float* gm0 = (const float*)d_in[6];
    const float* be0 = (const float*)d_in[7];
    const float* w1  = (const float*)d_in[8];
    const float* b1  = (const float*)d_in[9];
    const float* gm1 = (const float*)d_in[10];
    const float* be1 = (const float*)d_in[11];
    const float* w2  = (const float*)d_in[12];
    const float* b2  = (const float*)d_in[13];
    const float* gm2 = (const float*)d_in[14];
    const float* be2 = (const float*)d_in[15];
    const float* wl  = (const float*)d_in[16];
    const float* bl  = (const float*)d_in[17];
    const float* gl  = (const float*)d_in[18];
    const float* bel = (const float*)d_in[19];
    float* out = (float*)d_out;

    static int inited = 0;
    if (!inited) {
        cudaFuncSetAttribute(k_gemm_mma, cudaFuncAttributeMaxDynamicSharedMemorySize,
                             GEMM_SMEM);
        inited = 1;
    }

    dim3 gFuse(Nn / 32, Bn);
    k_fuse<<<gFuse, 256>>>(xyz, points);

    k_prepB<<<(DOUT * KPAD + 255) / 256, 256>>>(wl);

    dim3 gAgg(Sn, Bn);
    k_agg<<<gAgg, 128>>>(nn_idx, new_xyz,
                         w0, b0, gm0, be0,
                         w1, b1, gm1, be1,
                         w2, b2, gm2, be2);

    k_gemm_mma<<<(Bn * Sn) / 64, 256, GEMM_SMEM>>>(bl, gl, bel, out);
}

// round 7
// speedup vs baseline: 1.0613x; 1.0613x over previous
#include <cuda_runtime.h>
#include <cuda_bf16.h>
#include <cstdint>

#define Bn   16
#define Nn   16384
#define Sn   4096
#define Kn   16
#define FC   68      // fused channels: 64 points + 3 xyz + 1 pad
#define CMID 16
#define DOUT 128
#define AGGD 1072    // 67*16
#define KPAD 1088    // 34 * 32

// Scratch (no allocations allowed -> __device__ globals; zero-initialized)
__device__ float g_fused[(size_t)Bn * Nn * FC];              // ~71 MB
__device__ __nv_bfloat16 g_Ahi[(size_t)Bn * Sn * KPAD];      // agg hi split
__device__ __nv_bfloat16 g_Alo[(size_t)Bn * Sn * KPAD];      // agg lo split
__device__ __nv_bfloat16 g_Bhi[DOUT * KPAD];                 // wl^T hi split
__device__ __nv_bfloat16 g_Blo[DOUT * KPAD];                 // wl^T lo split

__device__ __forceinline__ uint32_t smem_u32(const void* p) {
    uint32_t a;
    asm("{ .reg .u64 t; cvta.to.shared.u64 t, %1; cvt.u32.u64 %0, t; }" : "=r"(a) : "l"(p));
    return a;
}

#define LDMX4(r0, r1, r2, r3, addr)                                            \
    asm volatile("ldmatrix.sync.aligned.m8n8.x4.shared.b16 {%0,%1,%2,%3}, [%4];" \
                 : "=r"(r0), "=r"(r1), "=r"(r2), "=r"(r3) : "r"(addr))

#define MMA16816(acc, a, b0, b1)                                               \
    asm volatile("mma.sync.aligned.m16n8k16.row.col.f32.bf16.bf16.f32 "        \
                 "{%0,%1,%2,%3},{%4,%5,%6,%7},{%8,%9},{%0,%1,%2,%3};"          \
                 : "+f"((acc)[0]), "+f"((acc)[1]), "+f"((acc)[2]), "+f"((acc)[3]) \
                 : "r"((a)[0]), "r"((a)[1]), "r"((a)[2]), "r"((a)[3]),         \
                   "r"(b0), "r"(b1))

#define CP16(dst, src)                                                         \
    asm volatile("cp.async.cg.shared.global [%0], [%1], 16;" :: "r"(dst), "l"(src))
#define CP_COMMIT() asm volatile("cp.async.commit_group;" ::: "memory")
#define CP_WAIT(n)  asm volatile("cp.async.wait_group %0;" :: "n"(n) : "memory")

// ===========================================================================
// Kernel 0: point-major fused feature array
// ===========================================================================
__global__ void k_fuse(const float* __restrict__ xyz, const float* __restrict__ points)
{
    __shared__ float t[32][69];
    int b = blockIdx.y, n0 = blockIdx.x * 32;
    for (int i = threadIdx.x; i < 68 * 32; i += 256) {
        int c = i >> 5, nn = i & 31;
        int n = n0 + nn;
        float v = 0.f;
        if (c < 64)      v = points[(b * 64 + c) * Nn + n];
        else if (c < 67) v = xyz[(b * 3 + (c - 64)) * Nn + n];
        t[nn][c] = v;
    }
    __syncthreads();
    float* dst = g_fused + ((size_t)b * Nn + n0) * FC;
    for (int i = threadIdx.x; i < 32 * 68; i += 256) {
        dst[i] = t[i / 68][i % 68];
    }
}

// ===========================================================================
// LayerNorm (+ leaky 0.2) helper
// ===========================================================================
template <int NCH>
__device__ __forceinline__ void ln_leaky(float* h, const float* gmm, const float* bt)
{
    const float inv = 1.f / (float)NCH;
    float m = 0.f;
#pragma unroll
    for (int j = 0; j < NCH; j++) m += h[j];
    m *= inv;
    float v = 0.f;
#pragma unroll
    for (int j = 0; j < NCH; j++) { float d = h[j] - m; v += d * d; }
    v *= inv;
    float r = rsqrtf(v + 1e-5f);
#pragma unroll
    for (int j = 0; j < NCH; j++) {
        float y = (h[j] - m) * r * gmm[j] + bt[j];
        h[j] = y > 0.f ? y : 0.2f * y;
    }
}

// ===========================================================================
// Kernel 1 v3: 8 points per CTA (128 threads). thread = (point pp, neighbor k)
//   -> MLP runs on ALL threads. Aggregation: thread owns fixed m-pair,
//   wk cached in registers, coalesced stores.
// ===========================================================================
#define PPB 8        // points per block
__global__ __launch_bounds__(128)
void k_agg(const int* __restrict__ nn_idx, const float* __restrict__ new_xyz,
           const float* __restrict__ w0, const float* __restrict__ b0,
           const float* __restrict__ gm0, const float* __restrict__ be0,
           const float* __restrict__ w1, const float* __restrict__ b1,
           const float* __restrict__ gm1, const float* __restrict__ be1,
           const float* __restrict__ w2, const float* __restrict__ b2,
           const float* __restrict__ gm2, const float* __restrict__ be2)
{
    __shared__ float g[PPB][17][FC];     // 17 rows: row 16 is pad (bank stagger)
    __shared__ float wk[PPB][Kn][17];
    __shared__ int   idxs[PPB * Kn];
    __shared__ float nx[PPB][3];
    __shared__ float wp[312];

    int s0 = blockIdx.x * PPB, b = blockIdx.y;
    int tid = threadIdx.x;
    int pp = tid >> 4, kk = tid & 15;

    idxs[tid] = nn_idx[((size_t)b * Sn + s0) * Kn + tid];   // 128 consecutive ints
    if (tid < 24) {
        int d = tid >> 3, q = tid & 7;
        nx[q][d] = new_xyz[(b * 3 + d) * Sn + s0 + q];
    }

    if (tid < 24) wp[tid] = w0[tid];
    if (tid < 8) {
        wp[24 + tid] = b0[tid];  wp[32 + tid] = gm0[tid]; wp[40 + tid] = be0[tid];
        wp[112 + tid] = b1[tid]; wp[120 + tid] = gm1[tid]; wp[128 + tid] = be1[tid];
    }
    if (tid < 64) wp[48 + tid] = w1[tid];
    wp[136 + tid] = w2[tid];
    if (tid < 16) {
        wp[264 + tid] = b2[tid]; wp[280 + tid] = gm2[tid]; wp[296 + tid] = be2[tid];
    }
    __syncthreads();

    // Gather: 8 points x 16 neighbors x 17 float4 = 2176 float4, 17 per thread
#pragma unroll
    for (int it = 0; it < 17; it++) {
        int i = tid + it * 128;
        int pg = i / 272;
        int rem = i - pg * 272;
        int kg = rem / 17;
        int cg = rem - kg * 17;
        const float4* src = (const float4*)(g_fused + ((size_t)b * Nn + idxs[pg * 16 + kg]) * FC);
        ((float4*)(&g[pg][kg][0]))[cg] = src[cg];
    }
    __syncthreads();

    // MLP: all 128 threads, one (point, neighbor) each
    {
        float x0 = g[pp][kk][64] - nx[pp][0];
        float x1 = g[pp][kk][65] - nx[pp][1];
        float x2 = g[pp][kk][66] - nx[pp][2];
        g[pp][kk][64] = x0; g[pp][kk][65] = x1; g[pp][kk][66] = x2;

        float h[8];
#pragma unroll
        for (int j = 0; j < 8; j++)
            h[j] = x0 * wp[j] + x1 * wp[8 + j] + x2 * wp[16 + j] + wp[24 + j];
        ln_leaky<8>(h, wp + 32, wp + 40);

        float h2[8];
#pragma unroll
        for (int j = 0; j < 8; j++) {
            float a = wp[112 + j];
#pragma unroll
            for (int r = 0; r < 8; r++) a += h[r] * wp[48 + r * 8 + j];
            h2[j] = a;
        }
        ln_leaky<8>(h2, wp + 120, wp + 128);

        float h3[16];
#pragma unroll
        for (int j = 0; j < 16; j++) {
            float a = wp[264 + j];
#pragma unroll
            for (int r = 0; r < 8; r++) a += h2[r] * wp[136 + r * 16 + j];
            h3[j] = a;
        }
        ln_leaky<16>(h3, wp + 280, wp + 296);
#pragma unroll
        for (int j = 0; j < 16; j++) wk[pp][kk][j] = h3[j];
    }
    __syncthreads();

    // Aggregation: thread = (point pp, slot t). p = t&7 fixed -> wk in regs.
    // output pair index ip = t + 16*i  (c = ip>>3, p = ip&7), coalesced stores.
    {
        int t = kk;
        int p = t & 7;
        float wr0[Kn], wr1[Kn];
#pragma unroll
        for (int k = 0; k < Kn; k++) { wr0[k] = wk[pp][k][2 * p]; wr1[k] = wk[pp][k][2 * p + 1]; }

        uint32_t* hrow = (uint32_t*)(g_Ahi + ((size_t)b * Sn + s0 + pp) * KPAD);
        uint32_t* lrow = (uint32_t*)(g_Alo + ((size_t)b * Sn + s0 + pp) * KPAD);
        for (int ip = t; ip < 536; ip += 16) {
            int c = ip >> 3;
            float v0 = 0.f, v1 = 0.f;
#pragma unroll
            for (int k = 0; k < Kn; k++) {
                float fv = g[pp][k][c];
                v0 += fv * wr0[k];
                v1 += fv * wr1[k];
            }
            __nv_bfloat16 h0 = __float2bfloat16(v0);
            __nv_bfloat16 h1 = __float2bfloat16(v1);
            __nv_bfloat16 l0 = __float2bfloat16(v0 - __bfloat162float(h0));
            __nv_bfloat16 l1 = __float2bfloat16(v1 - __bfloat162float(h1));
            hrow[ip] = (uint32_t)*(unsigned short*)&h0 | ((uint32_t)*(unsigned short*)&h1 << 16);
            lrow[ip] = (uint32_t)*(unsigned short*)&l0 | ((uint32_t)*(unsigned short*)&l1 << 16);
        }
    }
}

// ===========================================================================
// Kernel 1.5: transpose wl [1072][128] -> [128][1088], split bf16 hi/lo
// ===========================================================================
__global__ void k_prepB(const float* __restrict__ wl)
{
    int idx = blockIdx.x * 256 + threadIdx.x;
    if (idx >= DOUT * KPAD) return;
    int n = idx / KPAD, k = idx - n * KPAD;
    float v = (k < AGGD) ? wl[k * DOUT + n] : 0.f;
    __nv_bfloat16 h = __float2bfloat16(v);
    __nv_bfloat16 l = __float2bfloat16(v - __bfloat162float(h));
    g_Bhi[idx] = h;
    g_Blo[idx] = l;
}

// ===========================================================================
// Kernel 2: pipelined mma.sync bf16x3 GEMM [65536,1088]x[1088,128]
//   CTA tile 128x128, 256 thr (8 warps: 4m x 2n, warp tile 32x64).
//   K: 34 chunks of 32; cp.async double buffer, one barrier per chunk.
//   Term order HH -> LH -> (reload Blo over Bhi regs) -> HL.
// ===========================================================================
#define PITCHB   48          // bytes per smem row
#define A_SUB    6144        // 128 rows * 48B
#define B_SUB    6144        // 128 rows * 48B
#define B_BASE   24576       // 4 A sub-blocks
#define STAGEB   49152
#define GEMM_SMEM (2 * STAGEB)
#define TPITCH   129

__global__ __launch_bounds__(256, 2)
void k_gemm_mma(const float* __restrict__ bl, const float* __restrict__ gl,
                const float* __restrict__ bel, float* __restrict__ out)
{
    extern __shared__ char dsm[];
    __shared__ float spb[DOUT], spg[DOUT], spe[DOUT];

    int tid = threadIdx.x;
    int wid = tid >> 5, lane = tid & 31;
    int wm = wid & 3, wn = wid >> 2;       // warp tile rows wm*32, cols wn*64
    int m0 = blockIdx.x * 128;

    if (tid < DOUT) { spb[tid] = bl[tid]; spg[tid] = gl[tid]; spe[tid] = bel[tid]; }

    uint32_t sb = smem_u32(dsm);
    uint32_t aOff = (uint32_t)((lane & 15) * PITCHB + (lane >> 4) * 16);
    uint32_t bOff = (uint32_t)(((lane >> 4) * 8 + (lane & 7)) * PITCHB + ((lane >> 3) & 1) * 16);

    float acc[2][8][4];
#pragma unroll
    for (int f = 0; f < 2; f++)
#pragma unroll
        for (int q = 0; q < 8; q++)
#pragma unroll
            for (int r = 0; r < 4; r++) acc[f][q][r] = 0.f;

    auto stage_copy = [&](int st, int c) {
        uint32_t stu = sb + st * STAGEB;
#pragma unroll
        for (int t = tid; t < 1024; t += 256) {         // A: hi/lo, 2 sub, 128 rows, 2 halves
            int p = t >> 9, rem = t & 511, j = rem >> 8, r2 = rem & 255;
            int r = r2 >> 1, h = r2 & 1;
            const __nv_bfloat16* gA = p ? g_Alo : g_Ahi;
            const __nv_bfloat16* src = gA + (size_t)(m0 + r) * KPAD + c * 32 + j * 16 + h * 8;
            CP16(stu + (p * 2 + j) * A_SUB + r * PITCHB + h * 16, (const void*)src);
        }
#pragma unroll
        for (int t = tid; t < 1024; t += 256) {         // B: hi/lo, 2 sub, 128 rows, 2 halves
            int p = t >> 9, rem = t & 511, j = rem >> 8, r2 = rem & 255;
            int n = r2 >> 1, h = r2 & 1;
            const __nv_bfloat16* gB = p ? g_Blo : g_Bhi;
            const __nv_bfloat16* src = gB + (size_t)n * KPAD + c * 32 + j * 16 + h * 8;
            CP16(stu + B_BASE + (p * 2 + j) * B_SUB + n * PITCHB + h * 16, (const void*)src);
        }
    };

    stage_copy(0, 0);
    CP_COMMIT();

    for (int c = 0; c < 34; c++) {
        CP_WAIT(0);
        __syncthreads();
        if (c + 1 < 34) { stage_copy((c + 1) & 1, c + 1); CP_COMMIT(); }

        uint32_t stu = sb + (c & 1) * STAGEB;
#pragma unroll
        for (int j = 0; j < 2; j++) {
            uint32_t ahi[2][4], alo[2][4], bfr[4][4];
#pragma unroll
            for (int f = 0; f < 2; f++) {
                uint32_t ra = (uint32_t)((wm * 32 + f * 16) * PITCHB) + aOff;
                LDMX4(ahi[f][0], ahi[f][1], ahi[f][2], ahi[f][3], stu + j * A_SUB + ra);
                LDMX4(alo[f][0], alo[f][1], alo[f][2], alo[f][3], stu + (2 + j) * A_SUB + ra);
            }
            // B-hi fragments (4 n16 groups)
#pragma unroll
            for (int g = 0; g < 4; g++) {
                uint32_t rb = (uint32_t)((wn * 64 + g * 16) * PITCHB) + bOff;
                LDMX4(bfr[g][0], bfr[g][1], bfr[g][2], bfr[g][3], stu + B_BASE + j * B_SUB + rb);
            }
            // HH
#pragma unroll
            for (int g = 0; g < 4; g++)
#pragma unroll
                for (int f = 0; f < 2; f++) {
                    MMA16816(acc[f][2 * g],     ahi[f], bfr[g][0], bfr[g][1]);
                    MMA16816(acc[f][2 * g + 1], ahi[f], bfr[g][2], bfr[g][3]);
                }
            // LH
#pragma unroll
            for (int g = 0; g < 4; g++)
#pragma unroll
                for (int f = 0; f < 2; f++) {
                    MMA16816(acc[f][2 * g],     alo[f], bfr[g][0], bfr[g][1]);
                    MMA16816(acc[f][2 * g + 1], alo[f], bfr[g][2], bfr[g][3]);
                }
            // reload B-lo into same regs
#pragma unroll
            for (int g = 0; g < 4; g++) {
                uint32_t rb = (uint32_t)((wn * 64 + g * 16) * PITCHB) + bOff;
                LDMX4(bfr[g][0], bfr[g][1], bfr[g][2], bfr[g][3], stu + B_BASE + (2 + j) * B_SUB + rb);
            }
            // HL
#pragma unroll
            for (int g = 0; g < 4; g++)
#pragma unroll
                for (int f = 0; f < 2; f++) {
                    MMA16816(acc[f][2 * g],     ahi[f], bfr[g][0], bfr[g][1]);
                    MMA16816(acc[f][2 * g + 1], ahi[f], bfr[g][2], bfr[g][3]);
                }
        }
    }
    __syncthreads();     // all warps done with stage buffers before reusing dsm as T

    // ---- epilogue: acc (+bias) -> T[128][129] ----
    float* T = (float*)dsm;
#pragma unroll
    for (int f = 0; f < 2; f++) {
        int r0 = wm * 32 + f * 16 + (lane >> 2);
#pragma unroll
        for (int q = 0; q < 8; q++) {
            int d = wn * 64 + q * 8 + (lane & 3) * 2;
            T[r0 * TPITCH + d]           = acc[f][q][0] + spb[d];
            T[r0 * TPITCH + d + 1]       = acc[f][q][1] + spb[d + 1];
            T[(r0 + 8) * TPITCH + d]     = acc[f][q][2] + spb[d];
            T[(r0 + 8) * TPITCH + d + 1] = acc[f][q][3] + spb[d + 1];
        }
    }
    __syncthreads();

    // ---- LayerNorm: 2 lanes per row (64 cols each) ----
    {
        int r = tid >> 1, q = tid & 1;
        float v[64];
        float s1 = 0.f, s2 = 0.f;
#pragma unroll
        for (int i = 0; i < 64; i++) {
            v[i] = T[r * TPITCH + q * 64 + i];
            s1 += v[i]; s2 += v[i] * v[i];
        }
        s1 += __shfl_xor_sync(0xffffffffu, s1, 1);
        s2 += __shfl_xor_sync(0xffffffffu, s2, 1);
        float mean = s1 * (1.f / 128.f);
        float var  = s2 * (1.f / 128.f) - mean * mean;
        float rs   = rsqrtf(var + 1e-5f);
#pragma unroll
        for (int i = 0; i < 64; i++) {
            int d = q * 64 + i;
            float y = (v[i] - mean) * rs * spg[d] + spe[d];
            T[r * TPITCH + d] = y > 0.f ? y : 0.2f * y;
        }
    }
    __syncthreads();

    // ---- coalesced transposed store ----
    int b = m0 >> 12, s0 = m0 & 4095;
    float* ob = out + (size_t)b * DOUT * Sn + s0;
    for (int i = tid; i < 128 * DOUT; i += 256) {
        int d = i >> 7, r = i & 127;
        ob[(size_t)d * Sn + r] = T[r * TPITCH + d];
    }
}

// ===========================================================================
extern "C" void kernel_launch(void* const* d_in, const int* in_sizes, int n_in,
                              void* d_out, int out_size)
{
    const float* xyz     = (const float*)d_in[0];
    const float* points  = (const float*)d_in[1];
    const float* new_xyz = (const float*)d_in[2];
    const int*   nn_idx  = (const int*)  d_in[3];
    const float* w0  = (const float*)d_in[4];
    const float* b0  = (const float*)d_in[5];
    const float* gm0 = (const float*)d_in[6];
    const float* be0 = (const float*)d_in[7];
    const float* w1  = (const float*)d_in[8];
    const float* b1  = (const float*)d_in[9];
    const float* gm1 = (const float*)d_in[10];
    const float* be1 = (const float*)d_in[11];
    const float* w2  = (const float*)d_in[12];
    const float* b2  = (const float*)d_in[13];
    const float* gm2 = (const float*)d_in[14];
    const float* be2 = (const float*)d_in[15];
    const float* wl  = (const float*)d_in[16];
    const float* bl  = (const float*)d_in[17];
    const float* gl  = (const float*)d_in[18];
    const float* bel = (const float*)d_in[19];
    float* out = (float*)d_out;

    static int inited = 0;
    if (!inited) {
        cudaFuncSetAttribute(k_gemm_mma, cudaFuncAttributeMaxDynamicSharedMemorySize,
                             GEMM_SMEM);
        inited = 1;
    }

    dim3 gFuse(Nn / 32, Bn);
    k_fuse<<<gFuse, 256>>>(xyz, points);

    k_prepB<<<(DOUT * KPAD + 255) / 256, 256>>>(wl);

    dim3 gAgg(Sn / PPB, Bn);
    k_agg<<<gAgg, 128>>>(nn_idx, new_xyz,
                         w0, b0, gm0, be0,
                         w1, b1, gm1, be1,
                         w2, b2, gm2, be2);

    k_gemm_mma<<<(Bn * Sn) / 128, 256, GEMM_SMEM>>>(bl, gl, bel, out);
}

// round 8
// speedup vs baseline: 1.1740x; 1.1062x over previous
#include <cuda_runtime.h>
#include <cuda_bf16.h>
#include <cstdint>

#define Bn   16
#define Nn   16384
#define Sn   4096
#define Kn   16
#define FC   68      // fused channels: 64 points + 3 xyz + 1 pad
#define CMID 16
#define DOUT 128
#define AGGD 1072    // 67*16
#define KPAD 1088    // 34 * 32

// Scratch (no allocations allowed -> __device__ globals; zero-initialized)
__device__ float g_fused[(size_t)Bn * Nn * FC];              // ~71 MB
__device__ __nv_bfloat16 g_Ahi[(size_t)Bn * Sn * KPAD];      // agg hi split
__device__ __nv_bfloat16 g_Alo[(size_t)Bn * Sn * KPAD];      // agg lo split
__device__ __nv_bfloat16 g_Bhi[DOUT * KPAD];                 // wl^T hi split
__device__ __nv_bfloat16 g_Blo[DOUT * KPAD];                 // wl^T lo split

__device__ __forceinline__ uint32_t smem_u32(const void* p) {
    uint32_t a;
    asm("{ .reg .u64 t; cvta.to.shared.u64 t, %1; cvt.u32.u64 %0, t; }" : "=r"(a) : "l"(p));
    return a;
}

#define LDMX4(r0, r1, r2, r3, addr)                                            \
    asm volatile("ldmatrix.sync.aligned.m8n8.x4.shared.b16 {%0,%1,%2,%3}, [%4];" \
                 : "=r"(r0), "=r"(r1), "=r"(r2), "=r"(r3) : "r"(addr))

#define MMA16816(acc, a, b0, b1)                                               \
    asm volatile("mma.sync.aligned.m16n8k16.row.col.f32.bf16.bf16.f32 "        \
                 "{%0,%1,%2,%3},{%4,%5,%6,%7},{%8,%9},{%0,%1,%2,%3};"          \
                 : "+f"((acc)[0]), "+f"((acc)[1]), "+f"((acc)[2]), "+f"((acc)[3]) \
                 : "r"((a)[0]), "r"((a)[1]), "r"((a)[2]), "r"((a)[3]),         \
                   "r"(b0), "r"(b1))

#define CP16(dst, src)                                                         \
    asm volatile("cp.async.cg.shared.global [%0], [%1], 16;" :: "r"(dst), "l"(src))
#define CP_COMMIT() asm volatile("cp.async.commit_group;" ::: "memory")
#define CP_WAIT(n)  asm volatile("cp.async.wait_group %0;" :: "n"(n) : "memory")

#define FMA_F32X2(d, a, b, c)                                                  \
    asm("fma.rn.f32x2 %0, %1, %2, %3;"                                         \
        : "=l"(d) : "l"(a), "l"(b), "l"(c))

// ===========================================================================
// Kernel 0: point-major fused feature array (vectorized)
// ===========================================================================
__global__ void k_fuse(const float* __restrict__ xyz, const float* __restrict__ points)
{
    __shared__ float t[32][69];
    int b = blockIdx.y, n0 = blockIdx.x * 32;
    for (int i = threadIdx.x; i < 544; i += 256) {
        int c = i >> 3, nq = i & 7;
        float4 v = make_float4(0.f, 0.f, 0.f, 0.f);
        if (c < 64)
            v = *(const float4*)&points[((size_t)b * 64 + c) * Nn + n0 + nq * 4];
        else if (c < 67)
            v = *(const float4*)&xyz[((size_t)b * 3 + (c - 64)) * Nn + n0 + nq * 4];
        t[nq * 4 + 0][c] = v.x;
        t[nq * 4 + 1][c] = v.y;
        t[nq * 4 + 2][c] = v.z;
        t[nq * 4 + 3][c] = v.w;
    }
    __syncthreads();
    float* dst = g_fused + ((size_t)b * Nn + n0) * FC;
    for (int i = threadIdx.x; i < 544; i += 256) {
        int r = i / 17, q = i - r * 17;
        float4 v = make_float4(t[r][q * 4], t[r][q * 4 + 1],
                               t[r][q * 4 + 2], t[r][q * 4 + 3]);
        *(float4*)&dst[r * FC + q * 4] = v;
    }
}

// ===========================================================================
// LayerNorm (+ leaky 0.2) helper
// ===========================================================================
template <int NCH>
__device__ __forceinline__ void ln_leaky(float* h, const float* gmm, const float* bt)
{
    const float inv = 1.f / (float)NCH;
    float m = 0.f;
#pragma unroll
    for (int j = 0; j < NCH; j++) m += h[j];
    m *= inv;
    float v = 0.f;
#pragma unroll
    for (int j = 0; j < NCH; j++) { float d = h[j] - m; v += d * d; }
    v *= inv;
    float r = rsqrtf(v + 1e-5f);
#pragma unroll
    for (int j = 0; j < NCH; j++) {
        float y = (h[j] - m) * r * gmm[j] + bt[j];
        h[j] = y > 0.f ? y : 0.2f * y;
    }
}

// ===========================================================================
// Kernel 1: 8 points per CTA (128 threads). MLP on all threads; aggregation
//   uses packed fma.rn.f32x2 (c-pairs via LDS.64, fixed m-pair per thread).
// ===========================================================================
#define PPB 8        // points per block
__global__ __launch_bounds__(128)
void k_agg(const int* __restrict__ nn_idx, const float* __restrict__ new_xyz,
           const float* __restrict__ w0, const float* __restrict__ b0,
           const float* __restrict__ gm0, const float* __restrict__ be0,
           const float* __restrict__ w1, const float* __restrict__ b1,
           const float* __restrict__ gm1, const float* __restrict__ be1,
           const float* __restrict__ w2, const float* __restrict__ b2,
           const float* __restrict__ gm2, const float* __restrict__ be2)
{
    __shared__ float g[PPB][17][FC];
    __shared__ float wk[PPB][Kn][17];
    __shared__ int   idxs[PPB * Kn];
    __shared__ float nx[PPB][3];
    __shared__ float wp[312];

    int s0 = blockIdx.x * PPB, b = blockIdx.y;
    int tid = threadIdx.x;
    int pp = tid >> 4, kk = tid & 15;

    idxs[tid] = nn_idx[((size_t)b * Sn + s0) * Kn + tid];
    if (tid < 24) {
        int d = tid >> 3, q = tid & 7;
        nx[q][d] = new_xyz[(b * 3 + d) * Sn + s0 + q];
    }

    if (tid < 24) wp[tid] = w0[tid];
    if (tid < 8) {
        wp[24 + tid] = b0[tid];  wp[32 + tid] = gm0[tid]; wp[40 + tid] = be0[tid];
        wp[112 + tid] = b1[tid]; wp[120 + tid] = gm1[tid]; wp[128 + tid] = be1[tid];
    }
    if (tid < 64) wp[48 + tid] = w1[tid];
    wp[136 + tid] = w2[tid];
    if (tid < 16) {
        wp[264 + tid] = b2[tid]; wp[280 + tid] = gm2[tid]; wp[296 + tid] = be2[tid];
    }
    __syncthreads();

    // Gather: 8 points x 16 neighbors x 17 float4
#pragma unroll
    for (int it = 0; it < 17; it++) {
        int i = tid + it * 128;
        int pg = i / 272;
        int rem = i - pg * 272;
        int kg = rem / 17;
        int cg = rem - kg * 17;
        const float4* src = (const float4*)(g_fused + ((size_t)b * Nn + idxs[pg * 16 + kg]) * FC);
        ((float4*)(&g[pg][kg][0]))[cg] = src[cg];
    }
    __syncthreads();

    // MLP: all 128 threads, one (point, neighbor) each
    {
        float x0 = g[pp][kk][64] - nx[pp][0];
        float x1 = g[pp][kk][65] - nx[pp][1];
        float x2 = g[pp][kk][66] - nx[pp][2];
        g[pp][kk][64] = x0; g[pp][kk][65] = x1; g[pp][kk][66] = x2;

        float h[8];
#pragma unroll
        for (int j = 0; j < 8; j++)
            h[j] = x0 * wp[j] + x1 * wp[8 + j] + x2 * wp[16 + j] + wp[24 + j];
        ln_leaky<8>(h, wp + 32, wp + 40);

        float h2[8];
#pragma unroll
        for (int j = 0; j < 8; j++) {
            float a = wp[112 + j];
#pragma unroll
            for (int r = 0; r < 8; r++) a += h[r] * wp[48 + r * 8 + j];
            h2[j] = a;
        }
        ln_leaky<8>(h2, wp + 120, wp + 128);

        float h3[16];
#pragma unroll
        for (int j = 0; j < 16; j++) {
            float a = wp[264 + j];
#pragma unroll
            for (int r = 0; r < 8; r++) a += h2[r] * wp[136 + r * 16 + j];
            h3[j] = a;
        }
        ln_leaky<16>(h3, wp + 280, wp + 296);
#pragma unroll
        for (int j = 0; j < 16; j++) wk[pp][kk][j] = h3[j];
    }
    __syncthreads();

    // Aggregation: thread = (point pp, slot t). m-pair p = t&7 fixed; weights
    // splat-packed once. c handled in pairs via 64-bit loads + fma.rn.f32x2.
    {
        int t = kk;
        int p = t & 7;
        int cp0 = t >> 3;                 // 0 or 1

        unsigned long long ws0[Kn], ws1[Kn];
#pragma unroll
        for (int k = 0; k < Kn; k++) {
            float a0 = wk[pp][k][2 * p], a1 = wk[pp][k][2 * p + 1];
            asm("mov.b64 %0, {%1, %1};" : "=l"(ws0[k]) : "f"(a0));
            asm("mov.b64 %0, {%1, %1};" : "=l"(ws1[k]) : "f"(a1));
        }

        uint32_t* hrow = (uint32_t*)(g_Ahi + ((size_t)b * Sn + s0 + pp) * KPAD);
        uint32_t* lrow = (uint32_t*)(g_Alo + ((size_t)b * Sn + s0 + pp) * KPAD);

#pragma unroll 1
        for (int i = 0; i < 17; i++) {
            int cp = cp0 + 2 * i;         // 0..33
            int c = cp * 2;               // 0..66 (c+1 = 67 is zero pad)
            unsigned long long accA = 0ull, accB = 0ull;
#pragma unroll
            for (int k = 0; k < Kn; k++) {
                unsigned long long fv2 = *(const unsigned long long*)&g[pp][k][c];
                FMA_F32X2(accA, fv2, ws0[k], accA);
                FMA_F32X2(accB, fv2, ws1[k], accB);
            }
            float v00, v10, v01, v11;
            asm("mov.b64 {%0, %1}, %2;" : "=f"(v00), "=f"(v10) : "l"(accA));
            asm("mov.b64 {%0, %1}, %2;" : "=f"(v01), "=f"(v11) : "l"(accB));

            // row c: (m=2p -> v00, m=2p+1 -> v01); row c+1: (v10, v11)
            __nv_bfloat16 h00 = __float2bfloat16(v00);
            __nv_bfloat16 h01 = __float2bfloat16(v01);
            __nv_bfloat16 h10 = __float2bfloat16(v10);
            __nv_bfloat16 h11 = __float2bfloat16(v11);
            __nv_bfloat16 l00 = __float2bfloat16(v00 - __bfloat162float(h00));
            __nv_bfloat16 l01 = __float2bfloat16(v01 - __bfloat162float(h01));
            __nv_bfloat16 l10 = __float2bfloat16(v10 - __bfloat162float(h10));
            __nv_bfloat16 l11 = __float2bfloat16(v11 - __bfloat162float(h11));
            int ip0 = c * 8 + p, ip1 = (c + 1) * 8 + p;   // ip1 <= 543 (pad region ok, stores zeros)
            hrow[ip0] = (uint32_t)*(unsigned short*)&h00 | ((uint32_t)*(unsigned short*)&h01 << 16);
            hrow[ip1] = (uint32_t)*(unsigned short*)&h10 | ((uint32_t)*(unsigned short*)&h11 << 16);
            lrow[ip0] = (uint32_t)*(unsigned short*)&l00 | ((uint32_t)*(unsigned short*)&l01 << 16);
            lrow[ip1] = (uint32_t)*(unsigned short*)&l10 | ((uint32_t)*(unsigned short*)&l11 << 16);
        }
    }
}

// ===========================================================================
// Kernel 1.5: transpose wl [1072][128] -> [128][1088], split bf16 hi/lo
// ===========================================================================
__global__ void k_prepB(const float* __restrict__ wl)
{
    int idx = blockIdx.x * 256 + threadIdx.x;
    if (idx >= DOUT * KPAD) return;
    int n = idx / KPAD, k = idx - n * KPAD;
    float v = (k < AGGD) ? wl[k * DOUT + n] : 0.f;
    __nv_bfloat16 h = __float2bfloat16(v);
    __nv_bfloat16 l = __float2bfloat16(v - __bfloat162float(h));
    g_Bhi[idx] = h;
    g_Blo[idx] = l;
}

// ===========================================================================
// Kernel 2: pipelined mma.sync bf16x3 GEMM [65536,1088]x[1088,128]
//   (unchanged from R7 — near its mma.sync roofline)
// ===========================================================================
#define PITCHB   48
#define A_SUB    6144
#define B_SUB    6144
#define B_BASE   24576
#define STAGEB   49152
#define GEMM_SMEM (2 * STAGEB)
#define TPITCH   129

__global__ __launch_bounds__(256, 2)
void k_gemm_mma(const float* __restrict__ bl, const float* __restrict__ gl,
                const float* __restrict__ bel, float* __restrict__ out)
{
    extern __shared__ char dsm[];
    __shared__ float spb[DOUT], spg[DOUT], spe[DOUT];

    int tid = threadIdx.x;
    int wid = tid >> 5, lane = tid & 31;
    int wm = wid & 3, wn = wid >> 2;
    int m0 = blockIdx.x * 128;

    if (tid < DOUT) { spb[tid] = bl[tid]; spg[tid] = gl[tid]; spe[tid] = bel[tid]; }

    uint32_t sb = smem_u32(dsm);
    uint32_t aOff = (uint32_t)((lane & 15) * PITCHB + (lane >> 4) * 16);
    uint32_t bOff = (uint32_t)(((lane >> 4) * 8 + (lane & 7)) * PITCHB + ((lane >> 3) & 1) * 16);

    float acc[2][8][4];
#pragma unroll
    for (int f = 0; f < 2; f++)
#pragma unroll
        for (int q = 0; q < 8; q++)
#pragma unroll
            for (int r = 0; r < 4; r++) acc[f][q][r] = 0.f;

    auto stage_copy = [&](int st, int c) {
        uint32_t stu = sb + st * STAGEB;
#pragma unroll
        for (int t = tid; t < 1024; t += 256) {
            int p = t >> 9, rem = t & 511, j = rem >> 8, r2 = rem & 255;
            int r = r2 >> 1, h = r2 & 1;
            const __nv_bfloat16* gA = p ? g_Alo : g_Ahi;
            const __nv_bfloat16* src = gA + (size_t)(m0 + r) * KPAD + c * 32 + j * 16 + h * 8;
            CP16(stu + (p * 2 + j) * A_SUB + r * PITCHB + h * 16, (const void*)src);
        }
#pragma unroll
        for (int t = tid; t < 1024; t += 256) {
            int p = t >> 9, rem = t & 511, j = rem >> 8, r2 = rem & 255;
            int n = r2 >> 1, h = r2 & 1;
            const __nv_bfloat16* gB = p ? g_Blo : g_Bhi;
            const __nv_bfloat16* src = gB + (size_t)n * KPAD + c * 32 + j * 16 + h * 8;
            CP16(stu + B_BASE + (p * 2 + j) * B_SUB + n * PITCHB + h * 16, (const void*)src);
        }
    };

    stage_copy(0, 0);
    CP_COMMIT();

    for (int c = 0; c < 34; c++) {
        CP_WAIT(0);
        __syncthreads();
        if (c + 1 < 34) { stage_copy((c + 1) & 1, c + 1); CP_COMMIT(); }

        uint32_t stu = sb + (c & 1) * STAGEB;
#pragma unroll
        for (int j = 0; j < 2; j++) {
            uint32_t ahi[2][4], alo[2][4], bfr[4][4];
#pragma unroll
            for (int f = 0; f < 2; f++) {
                uint32_t ra = (uint32_t)((wm * 32 + f * 16) * PITCHB) + aOff;
                LDMX4(ahi[f][0], ahi[f][1], ahi[f][2], ahi[f][3], stu + j * A_SUB + ra);
                LDMX4(alo[f][0], alo[f][1], alo[f][2], alo[f][3], stu + (2 + j) * A_SUB + ra);
            }
#pragma unroll
            for (int g = 0; g < 4; g++) {
                uint32_t rb = (uint32_t)((wn * 64 + g * 16) * PITCHB) + bOff;
                LDMX4(bfr[g][0], bfr[g][1], bfr[g][2], bfr[g][3], stu + B_BASE + j * B_SUB + rb);
            }
            // HH
#pragma unroll
            for (int g = 0; g < 4; g++)
#pragma unroll
                for (int f = 0; f < 2; f++) {
                    MMA16816(acc[f][2 * g],     ahi[f], bfr[g][0], bfr[g][1]);
                    MMA16816(acc[f][2 * g + 1], ahi[f], bfr[g][2], bfr[g][3]);
                }
            // LH
#pragma unroll
            for (int g = 0; g < 4; g++)
#pragma unroll
                for (int f = 0; f < 2; f++) {
                    MMA16816(acc[f][2 * g],     alo[f], bfr[g][0], bfr[g][1]);
                    MMA16816(acc[f][2 * g + 1], alo[f], bfr[g][2], bfr[g][3]);
                }
            // reload B-lo into same regs
#pragma unroll
            for (int g = 0; g < 4; g++) {
                uint32_t rb = (uint32_t)((wn * 64 + g * 16) * PITCHB) + bOff;
                LDMX4(bfr[g][0], bfr[g][1], bfr[g][2], bfr[g][3], stu + B_BASE + (2 + j) * B_SUB + rb);
            }
            // HL
#pragma unroll
            for (int g = 0; g < 4; g++)
#pragma unroll
                for (int f = 0; f < 2; f++) {
                    MMA16816(acc[f][2 * g],     ahi[f], bfr[g][0], bfr[g][1]);
                    MMA16816(acc[f][2 * g + 1], ahi[f], bfr[g][2], bfr[g][3]);
                }
        }
    }
    __syncthreads();

    // ---- epilogue: acc (+bias) -> T[128][129] ----
    float* T = (float*)dsm;
#pragma unroll
    for (int f = 0; f < 2; f++) {
        int r0 = wm * 32 + f * 16 + (lane >> 2);
#pragma unroll
        for (int q = 0; q < 8; q++) {
            int d = wn * 64 + q * 8 + (lane & 3) * 2;
            T[r0 * TPITCH + d]           = acc[f][q][0] + spb[d];
            T[r0 * TPITCH + d + 1]       = acc[f][q][1] + spb[d + 1];
            T[(r0 + 8) * TPITCH + d]     = acc[f][q][2] + spb[d];
            T[(r0 + 8) * TPITCH + d + 1] = acc[f][q][3] + spb[d + 1];
        }
    }
    __syncthreads();

    // ---- LayerNorm: 2 lanes per row (64 cols each) ----
    {
        int r = tid >> 1, q = tid & 1;
        float v[64];
        float s1 = 0.f, s2 = 0.f;
#pragma unroll
        for (int i = 0; i < 64; i++) {
            v[i] = T[r * TPITCH + q * 64 + i];
            s1 += v[i]; s2 += v[i] * v[i];
        }
        s1 += __shfl_xor_sync(0xffffffffu, s1, 1);
        s2 += __shfl_xor_sync(0xffffffffu, s2, 1);
        float mean = s1 * (1.f / 128.f);
        float var  = s2 * (1.f / 128.f) - mean * mean;
        float rs   = rsqrtf(var + 1e-5f);
#pragma unroll
        for (int i = 0; i < 64; i++) {
            int d = q * 64 + i;
            float y = (v[i] - mean) * rs * spg[d] + spe[d];
            T[r * TPITCH + d] = y > 0.f ? y : 0.2f * y;
        }
    }
    __syncthreads();

    // ---- coalesced transposed store ----
    int b = m0 >> 12, s0 = m0 & 4095;
    float* ob = out + (size_t)b * DOUT * Sn + s0;
    for (int i = tid; i < 128 * DOUT; i += 256) {
        int d = i >> 7, r = i & 127;
        ob[(size_t)d * Sn + r] = T[r * TPITCH + d];
    }
}

// ===========================================================================
extern "C" void kernel_launch(void* const* d_in, const int* in_sizes, int n_in,
                              void* d_out, int out_size)
{
    const float* xyz     = (const float*)d_in[0];
    const float* points  = (const float*)d_in[1];
    const float* new_xyz = (const float*)d_in[2];
    const int*   nn_idx  = (const int*)  d_in[3];
    const float* w0  = (const float*)d_in[4];
    const float* b0  = (const float*)d_in[5];
    const float* gm0 = (const float*)d_in[6];
    const float* be0 = (const float*)d_in[7];
    const float* w1  = (const float*)d_in[8];
    const float* b1  = (const float*)d_in[9];
    const float* gm1 = (const float*)d_in[10];
    const float* be1 = (const float*)d_in[11];
    const float* w2  = (const float*)d_in[12];
    const float* b2  = (const float*)d_in[13];
    const float* gm2 = (const float*)d_in[14];
    const float* be2 = (const float*)d_in[15];
    const float* wl  = (const float*)d_in[16];
    const float* bl  = (const float*)d_in[17];
    const float* gl  = (const float*)d_in[18];
    const float* bel = (const float*)d_in[19];
    float* out = (float*)d_out;

    static int inited = 0;
    if (!inited) {
        cudaFuncSetAttribute(k_gemm_mma, cudaFuncAttributeMaxDynamicSharedMemorySize,
                             GEMM_SMEM);
        inited = 1;
    }

    dim3 gFuse(Nn / 32, Bn);
    k_fuse<<<gFuse, 256>>>(xyz, points);

    k_prepB<<<(DOUT * KPAD + 255) / 256, 256>>>(wl);

    dim3 gAgg(Sn / PPB, Bn);
    k_agg<<<gAgg, 128>>>(nn_idx, new_xyz,
                         w0, b0, gm0, be0,
                         w1, b1, gm1, be1,
                         w2, b2, gm2, be2);

    k_gemm_mma<<<(Bn * Sn) / 128, 256, GEMM_SMEM>>>(bl, gl, bel, out);
}